// round 4
// baseline (speedup 1.0000x reference)
#include <cuda_runtime.h>

// HBilinearUpsample: Poincare-ball geodesic bilinear upsample (c = 1).
// midpoint(x,y) = P*x + Q*y with (P,Q) from Gram scalars only;
// tanh(atanh(z)/2) = z/(1+sqrt(1-z^2)) -> no transcendentals.
//
// K1 gram   : float4 loads, 8-ch/warp, smem reduce, launch_bounds(256,5)
// K2 coeff  : per-cell 8 combination coefficients (packed float4 x2)
// K3 writer : 4 cells/thread -> 2 LDG.128 + 4 STG.128 per channel iter

static constexpr int B  = 8;
static constexpr int C  = 64;
static constexpr int H  = 128;
static constexpr int W  = 128;
static constexpr int HW = H * W;
static constexpr int CHW = C * HW;
static constexpr int Ho = 2 * H;
static constexpr int Wo = 2 * W;
static constexpr int HoWo = Ho * Wo;
static constexpr int NCELL = B * HW;

static constexpr int ZK  = 8;        // channel split for writer kernel
static constexpr int CPK = C / ZK;   // 8

#define EPS_F  1e-15f
#define MAXA_F 0.99999f   // 1 - 1e-5

// Summed Gram scalars: fields {n, dh, dv, dg, da} x NCELL = 2.6 MB
__device__ float g_sum[5][NCELL];
// Packed per-cell coefficients {Pa,Qa,Pv,Qv | C00,C10,C01,C11}: 4.2 MB
__device__ float4 cf[NCELL][2];

// ---------------------------------------------------------------------------
// K1: Gram sums. Block (32,8): tx covers W via 4 cells each (float4 loads),
// ty = 8-channel group. Warp shfl provides the w+4 neighbor element.
// ---------------------------------------------------------------------------
__global__ void __launch_bounds__(256, 5) gram_kernel(const float* __restrict__ x) {
    const int tx = threadIdx.x;          // 0..31
    const int ty = threadIdx.y;          // 0..7
    const int h  = blockIdx.x;
    const int b  = blockIdx.y;
    const int h1 = min(h + 1, H - 1);

    const float* row0 = x + b * CHW + ty * 8 * HW + h  * W + 4 * tx;
    const float* row1 = x + b * CHW + ty * 8 * HW + h1 * W + 4 * tx;

    float n0=0,n1=0,n2=0,n3=0, dh0=0,dh1=0,dh2=0,dh3=0;
    float dv0=0,dv1=0,dv2=0,dv3=0, dg0=0,dg1=0,dg2=0,dg3=0;
    float da0=0,da1=0,da2=0,da3=0;

#pragma unroll 4
    for (int c = 0; c < 8; c++) {
        const int o = c * HW;
        float4 v0 = *reinterpret_cast<const float4*>(row0 + o);
        float4 v1 = *reinterpret_cast<const float4*>(row1 + o);
        float e0 = __shfl_down_sync(0xffffffffu, v0.x, 1);
        float e1 = __shfl_down_sync(0xffffffffu, v1.x, 1);
        if (tx == 31) { e0 = v0.w; e1 = v1.w; }  // clamp at w = W-1

        n0  = fmaf(v0.x, v0.x, n0);   n1  = fmaf(v0.y, v0.y, n1);
        n2  = fmaf(v0.z, v0.z, n2);   n3  = fmaf(v0.w, v0.w, n3);
        dh0 = fmaf(v0.x, v0.y, dh0);  dh1 = fmaf(v0.y, v0.z, dh1);
        dh2 = fmaf(v0.z, v0.w, dh2);  dh3 = fmaf(v0.w, e0,   dh3);
        dv0 = fmaf(v0.x, v1.x, dv0);  dv1 = fmaf(v0.y, v1.y, dv1);
        dv2 = fmaf(v0.z, v1.z, dv2);  dv3 = fmaf(v0.w, v1.w, dv3);
        dg0 = fmaf(v0.x, v1.y, dg0);  dg1 = fmaf(v0.y, v1.z, dg1);
        dg2 = fmaf(v0.z, v1.w, dg2);  dg3 = fmaf(v0.w, e1,   dg3);
        da0 = fmaf(v0.y, v1.x, da0);  da1 = fmaf(v0.z, v1.y, da1);
        da2 = fmaf(v0.w, v1.z, da2);  da3 = fmaf(e0,   v1.w, da3);
    }

    // smem layout: red[ty][tx][f*4+j], f in {n,dh,dv,dg,da}
    __shared__ float red[8][32][20];
    float* r = red[ty][tx];
    r[0]=n0;  r[1]=n1;  r[2]=n2;  r[3]=n3;
    r[4]=dh0; r[5]=dh1; r[6]=dh2; r[7]=dh3;
    r[8]=dv0; r[9]=dv1; r[10]=dv2; r[11]=dv3;
    r[12]=dg0; r[13]=dg1; r[14]=dg2; r[15]=dg3;
    r[16]=da0; r[17]=da1; r[18]=da2; r[19]=da3;
    __syncthreads();

    const int tid = ty * 32 + tx;
    const int rowbase = (b * H + h) * W;
#pragma unroll
    for (int k = tid; k < 640; k += 256) {
        const int f = k >> 7;          // field 0..4
        const int w = k & 127;         // cell column
        const int fj = f * 4 + (w & 3);
        const int xw = w >> 2;
        float s = ((red[0][xw][fj] + red[1][xw][fj]) + (red[2][xw][fj] + red[3][xw][fj]))
                + ((red[4][xw][fj] + red[5][xw][fj]) + (red[6][xw][fj] + red[7][xw][fj]));
        g_sum[f][rowbase + w] = s;
    }
}

// ---------------------------------------------------------------------------
// midpoint(x,y) = P*x + Q*y given (|x|^2, |y|^2, <x,y>), c = 1.
// ---------------------------------------------------------------------------
__device__ __forceinline__ void mid_coeffs(float x2, float y2, float xy,
                                           float& P, float& Q) {
    float den1 = fmaxf(1.f - 2.f * xy + x2 * y2, EPS_F);
    float inv1 = __fdividef(1.f, den1);
    float A  = -(1.f - 2.f * xy + y2) * inv1;
    float Bc = (1.f - x2) * inv1;
    float w2 = A * A * x2 + 2.f * A * Bc * xy + Bc * Bc * y2;
    float wn = sqrtf(fmaxf(w2, EPS_F));
    float wc = fminf(wn, MAXA_F);
    float tau = __fdividef(wc, wn * (1.f + sqrtf(fmaxf(1.f - wc * wc, 0.f))));
    float Sa = tau * A;
    float Sb = tau * Bc;
    float xs = tau * (A * x2 + Bc * xy);
    float s2 = tau * tau * w2;
    float k = 1.f + 2.f * xs + s2;
    float den2 = fmaxf(1.f + 2.f * xs + x2 * s2, EPS_F);
    float inv2 = __fdividef(1.f, den2);
    P = (k + (1.f - x2) * Sa) * inv2;
    Q = (1.f - x2) * Sb * inv2;
}

// ---------------------------------------------------------------------------
// K2: per-cell coefficients. Thread per cell, grid (H, B).
// ---------------------------------------------------------------------------
__global__ void __launch_bounds__(128) coeff_kernel() {
    const int w = threadIdx.x;
    const int h = blockIdx.x;
    const int b = blockIdx.y;
    const int w1 = min(w + 1, W - 1);
    const int h1 = min(h + 1, H - 1);

    const int base = b * HW;
    const int i00 = base + h  * W + w;
    const int i10 = base + h  * W + w1;
    const int i01 = base + h1 * W + w;
    const int i11 = base + h1 * W + w1;

    const float n00 = g_sum[0][i00], n10 = g_sum[0][i10];
    const float n01 = g_sum[0][i01], n11 = g_sum[0][i11];
    const float dhT = g_sum[1][i00], dhB = g_sum[1][i01];
    const float dvL = g_sum[2][i00], dvR = g_sum[2][i10];
    const float dgd = g_sum[3][i00], dad = g_sum[4][i00];

    float Pa, Qa, Pv, Qv, Pb, Qb, Pc, Qc;
    mid_coeffs(n00, n10, dhT, Pa, Qa);   // a = mid(x00, x10)
    mid_coeffs(n00, n01, dvL, Pv, Qv);   // mid_v
    mid_coeffs(n01, n11, dhB, Pb, Qb);   // b = mid(x01, x11)

    float a2 = Pa * Pa * n00 + 2.f * Pa * Qa * dhT + Qa * Qa * n10;
    float b2 = Pb * Pb * n01 + 2.f * Pb * Qb * dhB + Qb * Qb * n11;
    float ab = Pa * Pb * dvL + Pa * Qb * dgd + Qa * Pb * dad + Qa * Qb * dvR;
    mid_coeffs(a2, b2, ab, Pc, Qc);      // center = mid(a, b)

    cf[i00][0] = make_float4(Pa, Qa, Pv, Qv);
    cf[i00][1] = make_float4(Pc * Pa, Pc * Qa, Qc * Pb, Qc * Qb);
}

// ---------------------------------------------------------------------------
// K3: writer. Block (32,4): each warp owns a full input row (4 cells/lane,
// float4 loads, shfl for the +1 neighbor). Per channel iter:
// 2 LDG.128 in, 4 STG.128 out. Grid (H/4, B, ZK); CPK channels per z.
// ---------------------------------------------------------------------------
__global__ void __launch_bounds__(128) upsample_kernel(const float* __restrict__ x,
                                                       float* __restrict__ out) {
    const int lane = threadIdx.x;                 // 0..31
    const int h = blockIdx.x * 4 + threadIdx.y;
    const int b = blockIdx.y;
    const int z = blockIdx.z;
    const int w0 = 4 * lane;
    const int h1 = min(h + 1, H - 1);

    const int idx0 = (b * H + h) * W + w0;
    const float4 k0a = cf[idx0    ][0], k0b = cf[idx0    ][1];
    const float4 k1a = cf[idx0 + 1][0], k1b = cf[idx0 + 1][1];
    const float4 k2a = cf[idx0 + 2][0], k2b = cf[idx0 + 2][1];
    const float4 k3a = cf[idx0 + 3][0], k3b = cf[idx0 + 3][1];

    const float* r0p = x + b * CHW + z * CPK * HW + h  * W + w0;
    const float* r1p = x + b * CHW + z * CPK * HW + h1 * W + w0;
    float* po = out + (size_t)b * C * HoWo + (size_t)z * CPK * HoWo;
    const int s0 = (2 * h) * Wo + 8 * lane;
    const int s1 = s0 + Wo;

#pragma unroll 2
    for (int c = 0; c < CPK; c++) {
        const int o = c * HW;
        float4 v0 = *reinterpret_cast<const float4*>(r0p + o);
        float4 v1 = *reinterpret_cast<const float4*>(r1p + o);
        float e0 = __shfl_down_sync(0xffffffffu, v0.x, 1);
        float e1 = __shfl_down_sync(0xffffffffu, v1.x, 1);
        if (lane == 31) { e0 = v0.w; e1 = v1.w; }   // clamp at w = W-1

        float4 tA, tB, bA, bB;
        tA.x = v0.x;
        tA.y = fmaf(k0a.x, v0.x, k0a.y * v0.y);
        tA.z = v0.y;
        tA.w = fmaf(k1a.x, v0.y, k1a.y * v0.z);
        tB.x = v0.z;
        tB.y = fmaf(k2a.x, v0.z, k2a.y * v0.w);
        tB.z = v0.w;
        tB.w = fmaf(k3a.x, v0.w, k3a.y * e0);

        bA.x = fmaf(k0a.z, v0.x, k0a.w * v1.x);
        bA.y = fmaf(k0b.x, v0.x, fmaf(k0b.y, v0.y, fmaf(k0b.z, v1.x, k0b.w * v1.y)));
        bA.z = fmaf(k1a.z, v0.y, k1a.w * v1.y);
        bA.w = fmaf(k1b.x, v0.y, fmaf(k1b.y, v0.z, fmaf(k1b.z, v1.y, k1b.w * v1.z)));
        bB.x = fmaf(k2a.z, v0.z, k2a.w * v1.z);
        bB.y = fmaf(k2b.x, v0.z, fmaf(k2b.y, v0.w, fmaf(k2b.z, v1.z, k2b.w * v1.w)));
        bB.z = fmaf(k3a.z, v0.w, k3a.w * v1.w);
        bB.w = fmaf(k3b.x, v0.w, fmaf(k3b.y, e0, fmaf(k3b.z, v1.w, k3b.w * e1)));

        const int oo = c * HoWo;
        *reinterpret_cast<float4*>(po + oo + s0)     = tA;
        *reinterpret_cast<float4*>(po + oo + s0 + 4) = tB;
        *reinterpret_cast<float4*>(po + oo + s1)     = bA;
        *reinterpret_cast<float4*>(po + oo + s1 + 4) = bB;
    }
}

extern "C" void kernel_launch(void* const* d_in, const int* in_sizes, int n_in,
                              void* d_out, int out_size) {
    const float* x = (const float*)d_in[0];
    float* out = (float*)d_out;
    (void)in_sizes; (void)n_in; (void)out_size;

    gram_kernel<<<dim3(H, B), dim3(32, 8)>>>(x);
    coeff_kernel<<<dim3(H, B), 128>>>();
    upsample_kernel<<<dim3(H / 4, B, ZK), dim3(32, 4)>>>(x, out);
}

// round 6
// speedup vs baseline: 1.2293x; 1.2293x over previous
#include <cuda_runtime.h>

// HBilinearUpsample: Poincare-ball geodesic bilinear upsample (c = 1).
// midpoint(x,y) = P*x + Q*y with (P,Q) from Gram scalars only;
// tanh(atanh(z)/2) = z/(1+sqrt(1-z^2)) -> no transcendentals.
//
// K1 gram   : 2 cells/thread (float2), 10 accumulators, 512-thread blocks,
//             ~30 regs -> full occupancy; smem reduce -> summed scratch
// K2 coeff  : per-cell 8 combination coefficients (packed float4 x2)
// K3 writer : 2 cells/thread, float2 loads, STG.128 stores (R3-proven)

static constexpr int B  = 8;
static constexpr int C  = 64;
static constexpr int H  = 128;
static constexpr int W  = 128;
static constexpr int HW = H * W;
static constexpr int CHW = C * HW;
static constexpr int Ho = 2 * H;
static constexpr int Wo = 2 * W;
static constexpr int HoWo = Ho * Wo;
static constexpr int NCELL = B * HW;

static constexpr int ZK  = 4;        // channel split for writer kernel
static constexpr int CPK = C / ZK;   // 16

#define EPS_F  1e-15f
#define MAXA_F 0.99999f   // 1 - 1e-5

// Summed Gram scalars: fields {n, dh, dv, dg, da} x NCELL = 2.6 MB
__device__ float g_sum[5][NCELL];
// Packed per-cell coefficients {Pa,Qa,Pv,Qv | C00,C10,C01,C11}: 4.2 MB
__device__ float4 cf[NCELL][2];

// ---------------------------------------------------------------------------
// K1: Gram sums. Block (64,8): tx handles 2 cells (float2), ty = 8-channel
// group. Neighbor (w+2) element read as a scalar (L1 hit). Grid (H, B).
// ---------------------------------------------------------------------------
__global__ void __launch_bounds__(512) gram_kernel(const float* __restrict__ x) {
    const int tx = threadIdx.x;          // 0..63
    const int ty = threadIdx.y;          // 0..7
    const int h  = blockIdx.x;
    const int b  = blockIdx.y;
    const int h1 = min(h + 1, H - 1);
    const int w0 = 2 * tx;
    const int w2 = min(w0 + 2, W - 1);   // clamped right neighbor of cell w0+1

    const float* base0 = x + b * CHW + ty * 8 * HW + h  * W;
    const float* base1 = x + b * CHW + ty * 8 * HW + h1 * W;

    float n0=0,n1=0, dh0=0,dh1=0, dv0=0,dv1=0, dg0=0,dg1=0, da0=0,da1=0;

#pragma unroll
    for (int c = 0; c < 8; c++) {
        const int o = c * HW;
        float2 v0 = *reinterpret_cast<const float2*>(base0 + o + w0);
        float2 v1 = *reinterpret_cast<const float2*>(base1 + o + w0);
        float  e0 = base0[o + w2];
        float  e1 = base1[o + w2];

        n0  = fmaf(v0.x, v0.x, n0);   n1  = fmaf(v0.y, v0.y, n1);
        dh0 = fmaf(v0.x, v0.y, dh0);  dh1 = fmaf(v0.y, e0,   dh1);
        dv0 = fmaf(v0.x, v1.x, dv0);  dv1 = fmaf(v0.y, v1.y, dv1);
        dg0 = fmaf(v0.x, v1.y, dg0);  dg1 = fmaf(v0.y, e1,   dg1);
        da0 = fmaf(v0.y, v1.x, da0);  da1 = fmaf(e0,   v1.y, da1);
    }

    // smem: red[ty][tx][f*2+j], f in {n,dh,dv,dg,da}, j in {0,1}
    __shared__ float red[8][64][10];
    float* r = red[ty][tx];
    r[0]=n0;  r[1]=n1;
    r[2]=dh0; r[3]=dh1;
    r[4]=dv0; r[5]=dv1;
    r[6]=dg0; r[7]=dg1;
    r[8]=da0; r[9]=da1;
    __syncthreads();

    const int tid = ty * 64 + tx;
    const int rowbase = (b * H + h) * W;
#pragma unroll
    for (int k = tid; k < 640; k += 512) {
        const int f = k >> 7;          // field 0..4
        const int w = k & 127;         // cell column
        const int fj = f * 2 + (w & 1);
        const int xw = w >> 1;
        float s = ((red[0][xw][fj] + red[1][xw][fj]) + (red[2][xw][fj] + red[3][xw][fj]))
                + ((red[4][xw][fj] + red[5][xw][fj]) + (red[6][xw][fj] + red[7][xw][fj]));
        g_sum[f][rowbase + w] = s;
    }
}

// ---------------------------------------------------------------------------
// midpoint(x,y) = P*x + Q*y given (|x|^2, |y|^2, <x,y>), c = 1.
// ---------------------------------------------------------------------------
__device__ __forceinline__ void mid_coeffs(float x2, float y2, float xy,
                                           float& P, float& Q) {
    float den1 = fmaxf(1.f - 2.f * xy + x2 * y2, EPS_F);
    float inv1 = __fdividef(1.f, den1);
    float A  = -(1.f - 2.f * xy + y2) * inv1;
    float Bc = (1.f - x2) * inv1;
    float w2 = A * A * x2 + 2.f * A * Bc * xy + Bc * Bc * y2;
    float wn = sqrtf(fmaxf(w2, EPS_F));
    float wc = fminf(wn, MAXA_F);
    float tau = __fdividef(wc, wn * (1.f + sqrtf(fmaxf(1.f - wc * wc, 0.f))));
    float Sa = tau * A;
    float Sb = tau * Bc;
    float xs = tau * (A * x2 + Bc * xy);
    float s2 = tau * tau * w2;
    float k = 1.f + 2.f * xs + s2;
    float den2 = fmaxf(1.f + 2.f * xs + x2 * s2, EPS_F);
    float inv2 = __fdividef(1.f, den2);
    P = (k + (1.f - x2) * Sa) * inv2;
    Q = (1.f - x2) * Sb * inv2;
}

// ---------------------------------------------------------------------------
// K2: per-cell coefficients. Thread per cell, grid (H, B).
// ---------------------------------------------------------------------------
__global__ void __launch_bounds__(128) coeff_kernel() {
    const int w = threadIdx.x;
    const int h = blockIdx.x;
    const int b = blockIdx.y;
    const int w1 = min(w + 1, W - 1);
    const int h1 = min(h + 1, H - 1);

    const int base = b * HW;
    const int i00 = base + h  * W + w;
    const int i10 = base + h  * W + w1;
    const int i01 = base + h1 * W + w;
    const int i11 = base + h1 * W + w1;

    const float n00 = g_sum[0][i00], n10 = g_sum[0][i10];
    const float n01 = g_sum[0][i01], n11 = g_sum[0][i11];
    const float dhT = g_sum[1][i00], dhB = g_sum[1][i01];
    const float dvL = g_sum[2][i00], dvR = g_sum[2][i10];
    const float dgd = g_sum[3][i00], dad = g_sum[4][i00];

    float Pa, Qa, Pv, Qv, Pb, Qb, Pc, Qc;
    mid_coeffs(n00, n10, dhT, Pa, Qa);   // a = mid(x00, x10)
    mid_coeffs(n00, n01, dvL, Pv, Qv);   // mid_v
    mid_coeffs(n01, n11, dhB, Pb, Qb);   // b = mid(x01, x11)

    float a2 = Pa * Pa * n00 + 2.f * Pa * Qa * dhT + Qa * Qa * n10;
    float b2 = Pb * Pb * n01 + 2.f * Pb * Qb * dhB + Qb * Qb * n11;
    float ab = Pa * Pb * dvL + Pa * Qb * dgd + Qa * Pb * dad + Qa * Qb * dvR;
    mid_coeffs(a2, b2, ab, Pc, Qc);      // center = mid(a, b)

    cf[i00][0] = make_float4(Pa, Qa, Pv, Qv);
    cf[i00][1] = make_float4(Pc * Pa, Pc * Qa, Qc * Pb, Qc * Qb);
}

// ---------------------------------------------------------------------------
// K3: writer. Block (64,2): tx handles 2 adjacent cells -> 4 contiguous
// outputs per row -> STG.128. Grid (H/2, B, ZK), 16 channels per z.
// ---------------------------------------------------------------------------
__global__ void __launch_bounds__(128) upsample_kernel(const float* __restrict__ x,
                                                       float* __restrict__ out) {
    const int t = threadIdx.x;                  // 0..63
    const int h = blockIdx.x * 2 + threadIdx.y;
    const int b = blockIdx.y;
    const int z = blockIdx.z;
    const int w0 = 2 * t;
    const int w2 = min(w0 + 2, W - 1);
    const int h1 = min(h + 1, H - 1);

    const int idx0 = (b * H + h) * W + w0;
    const float4 c0a = cf[idx0][0];     // Pa,Qa,Pv,Qv (cell 0)
    const float4 c0b = cf[idx0][1];     // C00,C10,C01,C11
    const float4 c1a = cf[idx0 + 1][0]; // cell 1
    const float4 c1b = cf[idx0 + 1][1];

    const float* px = x + b * CHW + z * CPK * HW;
    float* po = out + (size_t)b * C * HoWo + (size_t)z * CPK * HoWo;
    const int r0 = (2 * h) * Wo + 4 * t;
    const int r1 = r0 + Wo;
    const int q0 = h * W + w0;
    const int q2 = h * W + w2;
    const int s0 = h1 * W + w0;
    const int s2 = h1 * W + w2;

#pragma unroll 8
    for (int c = 0; c < CPK; c++) {
        const int o = c * HW;
        float2 a  = *reinterpret_cast<const float2*>(px + o + q0); // x00_0, x00_1(=x10_0)
        float  e0 = px[o + q2];                                    // x10_1
        float2 cc = *reinterpret_cast<const float2*>(px + o + s0); // x01_0, x01_1(=x11_0)
        float  e1 = px[o + s2];                                    // x11_1

        float4 top, bot;
        top.x = a.x;
        top.y = fmaf(c0a.x, a.x, c0a.y * a.y);
        top.z = a.y;
        top.w = fmaf(c1a.x, a.y, c1a.y * e0);
        bot.x = fmaf(c0a.z, a.x, c0a.w * cc.x);
        bot.y = fmaf(c0b.x, a.x, fmaf(c0b.y, a.y, fmaf(c0b.z, cc.x, c0b.w * cc.y)));
        bot.z = fmaf(c1a.z, a.y, c1a.w * cc.y);
        bot.w = fmaf(c1b.x, a.y, fmaf(c1b.y, e0, fmaf(c1b.z, cc.y, c1b.w * e1)));

        const int oo = c * HoWo;
        *reinterpret_cast<float4*>(po + oo + r0) = top;
        *reinterpret_cast<float4*>(po + oo + r1) = bot;
    }
}

extern "C" void kernel_launch(void* const* d_in, const int* in_sizes, int n_in,
                              void* d_out, int out_size) {
    const float* x = (const float*)d_in[0];
    float* out = (float*)d_out;
    (void)in_sizes; (void)n_in; (void)out_size;

    gram_kernel<<<dim3(H, B), dim3(64, 8)>>>(x);
    coeff_kernel<<<dim3(H, B), 128>>>();
    upsample_kernel<<<dim3(H / 2, B, ZK), dim3(64, 2)>>>(x, out);
}

// round 8
// speedup vs baseline: 1.3542x; 1.1016x over previous
#include <cuda_runtime.h>

// HBilinearUpsample: Poincare-ball geodesic bilinear upsample (c = 1).
// midpoint(x,y) = P*x + Q*y with (P,Q) from Gram scalars only;
// tanh(atanh(z)/2) = z/(1+sqrt(1-z^2)) -> no transcendentals.
//
// K1 gramcoeff : per (h,b) row-block loads rows h,h+1 across all channels,
//                accumulates 7 Gram fields for BOTH rows, smem-reduces, and
//                computes the 8 per-cell combination coefficients directly.
// K2 writer    : 2 cells/thread, float2 loads, STG.128 streaming stores.

static constexpr int B  = 8;
static constexpr int C  = 64;
static constexpr int H  = 128;
static constexpr int W  = 128;
static constexpr int HW = H * W;
static constexpr int CHW = C * HW;
static constexpr int Ho = 2 * H;
static constexpr int Wo = 2 * W;
static constexpr int HoWo = Ho * Wo;
static constexpr int NCELL = B * HW;

static constexpr int ZK  = 4;        // channel split for writer kernel
static constexpr int CPK = C / ZK;   // 16

#define EPS_F  1e-15f
#define MAXA_F 0.99999f   // 1 - 1e-5

// Packed per-cell coefficients {Pa,Qa,Pv,Qv | C00,C10,C01,C11}: 4.2 MB
__device__ float4 cf[NCELL][2];

// ---------------------------------------------------------------------------
// midpoint(x,y) = P*x + Q*y given (|x|^2, |y|^2, <x,y>), c = 1.
// Mirrors the reference clip chain.
// ---------------------------------------------------------------------------
__device__ __forceinline__ void mid_coeffs(float x2, float y2, float xy,
                                           float& P, float& Q) {
    float den1 = fmaxf(1.f - 2.f * xy + x2 * y2, EPS_F);
    float inv1 = __fdividef(1.f, den1);
    float A  = -(1.f - 2.f * xy + y2) * inv1;
    float Bc = (1.f - x2) * inv1;
    float w2 = A * A * x2 + 2.f * A * Bc * xy + Bc * Bc * y2;
    float wn = sqrtf(fmaxf(w2, EPS_F));
    float wc = fminf(wn, MAXA_F);
    float tau = __fdividef(wc, wn * (1.f + sqrtf(fmaxf(1.f - wc * wc, 0.f))));
    float Sa = tau * A;
    float Sb = tau * Bc;
    float xs = tau * (A * x2 + Bc * xy);
    float s2 = tau * tau * w2;
    float k = 1.f + 2.f * xs + s2;
    float den2 = fmaxf(1.f + 2.f * xs + x2 * s2, EPS_F);
    float inv2 = __fdividef(1.f, den2);
    P = (k + (1.f - x2) * Sa) * inv2;
    Q = (1.f - x2) * Sb * inv2;
}

// ---------------------------------------------------------------------------
// K1: fused Gram + coefficients. Block (64,8): tx handles 2 cells (float2),
// ty = 8-channel group. Accumulates 7 fields x 2 cells:
//   nA (|row_h|^2), nB (|row_h1|^2), hA (h-dot row h), hB (h-dot row h1),
//   v (vertical), g (diagonal), a (anti-diagonal)
// After smem reduce, 128 threads compute per-cell coefficients -> cf.
// ---------------------------------------------------------------------------
__global__ void __launch_bounds__(512) gramcoeff_kernel(const float* __restrict__ x) {
    const int tx = threadIdx.x;          // 0..63
    const int ty = threadIdx.y;          // 0..7
    const int h  = blockIdx.x;
    const int b  = blockIdx.y;
    const int h1 = min(h + 1, H - 1);
    const int w0 = 2 * tx;
    const int w2 = min(w0 + 2, W - 1);

    const float* base0 = x + b * CHW + ty * 8 * HW + h  * W;
    const float* base1 = x + b * CHW + ty * 8 * HW + h1 * W;

    float nA0=0,nA1=0, nB0=0,nB1=0, hA0=0,hA1=0, hB0=0,hB1=0;
    float v0_=0,v1_=0, g0_=0,g1_=0, a0_=0,a1_=0;

#pragma unroll
    for (int c = 0; c < 8; c++) {
        const int o = c * HW;
        float2 u = *reinterpret_cast<const float2*>(base0 + o + w0);
        float2 d = *reinterpret_cast<const float2*>(base1 + o + w0);
        float eu = base0[o + w2];
        float ed = base1[o + w2];

        nA0 = fmaf(u.x, u.x, nA0);  nA1 = fmaf(u.y, u.y, nA1);
        nB0 = fmaf(d.x, d.x, nB0);  nB1 = fmaf(d.y, d.y, nB1);
        hA0 = fmaf(u.x, u.y, hA0);  hA1 = fmaf(u.y, eu, hA1);
        hB0 = fmaf(d.x, d.y, hB0);  hB1 = fmaf(d.y, ed, hB1);
        v0_ = fmaf(u.x, d.x, v0_);  v1_ = fmaf(u.y, d.y, v1_);
        g0_ = fmaf(u.x, d.y, g0_);  g1_ = fmaf(u.y, ed, g1_);
        a0_ = fmaf(u.y, d.x, a0_);  a1_ = fmaf(eu, d.y, a1_);
    }

    // red[ty][tx][f*2+j], f in {nA,nB,hA,hB,v,g,a}
    __shared__ float red[8][64][14];
    __shared__ float fin[7][W];
    float* r = red[ty][tx];
    r[0]=nA0;  r[1]=nA1;
    r[2]=nB0;  r[3]=nB1;
    r[4]=hA0;  r[5]=hA1;
    r[6]=hB0;  r[7]=hB1;
    r[8]=v0_;  r[9]=v1_;
    r[10]=g0_; r[11]=g1_;
    r[12]=a0_; r[13]=a1_;
    __syncthreads();

    const int tid = ty * 64 + tx;
#pragma unroll
    for (int k = tid; k < 7 * W; k += 512) {
        const int f = k >> 7;          // field 0..6
        const int w = k & 127;         // cell column
        const int fj = f * 2 + (w & 1);
        const int xw = w >> 1;
        float s = ((red[0][xw][fj] + red[1][xw][fj]) + (red[2][xw][fj] + red[3][xw][fj]))
                + ((red[4][xw][fj] + red[5][xw][fj]) + (red[6][xw][fj] + red[7][xw][fj]));
        fin[f][w] = s;
    }
    __syncthreads();

    if (tid < W) {
        const int w  = tid;
        const int w1 = min(w + 1, W - 1);

        const float n00 = fin[0][w], n10 = fin[0][w1];
        const float n01 = fin[1][w], n11 = fin[1][w1];
        const float dhT = fin[2][w], dhB = fin[3][w];
        const float dvL = fin[4][w], dvR = fin[4][w1];
        const float dgd = fin[5][w], dad = fin[6][w];

        float Pa, Qa, Pv, Qv, Pb, Qb, Pc, Qc;
        mid_coeffs(n00, n10, dhT, Pa, Qa);   // a = mid(x00, x10)
        mid_coeffs(n00, n01, dvL, Pv, Qv);   // mid_v
        mid_coeffs(n01, n11, dhB, Pb, Qb);   // b = mid(x01, x11)

        float a2 = Pa * Pa * n00 + 2.f * Pa * Qa * dhT + Qa * Qa * n10;
        float b2 = Pb * Pb * n01 + 2.f * Pb * Qb * dhB + Qb * Qb * n11;
        float ab = Pa * Pb * dvL + Pa * Qb * dgd + Qa * Pb * dad + Qa * Qb * dvR;
        mid_coeffs(a2, b2, ab, Pc, Qc);      // center = mid(a, b)

        const int i00 = (b * H + h) * W + w;
        cf[i00][0] = make_float4(Pa, Qa, Pv, Qv);
        cf[i00][1] = make_float4(Pc * Pa, Pc * Qa, Qc * Pb, Qc * Qb);
    }
}

// ---------------------------------------------------------------------------
// K2: writer. Block (64,2): tx handles 2 adjacent cells -> 4 contiguous
// outputs per row -> STG.128 streaming. Grid (H/2, B, ZK), 16 ch per z.
// ---------------------------------------------------------------------------
__global__ void __launch_bounds__(128) upsample_kernel(const float* __restrict__ x,
                                                       float* __restrict__ out) {
    const int t = threadIdx.x;                  // 0..63
    const int h = blockIdx.x * 2 + threadIdx.y;
    const int b = blockIdx.y;
    const int z = blockIdx.z;
    const int w0 = 2 * t;
    const int w2 = min(w0 + 2, W - 1);
    const int h1 = min(h + 1, H - 1);

    const int idx0 = (b * H + h) * W + w0;
    const float4 c0a = cf[idx0][0];     // Pa,Qa,Pv,Qv (cell 0)
    const float4 c0b = cf[idx0][1];     // C00,C10,C01,C11
    const float4 c1a = cf[idx0 + 1][0]; // cell 1
    const float4 c1b = cf[idx0 + 1][1];

    const float* px = x + b * CHW + z * CPK * HW;
    float* po = out + (size_t)b * C * HoWo + (size_t)z * CPK * HoWo;
    const int r0 = (2 * h) * Wo + 4 * t;
    const int r1 = r0 + Wo;
    const int q0 = h * W + w0;
    const int q2 = h * W + w2;
    const int s0 = h1 * W + w0;
    const int s2 = h1 * W + w2;

#pragma unroll 8
    for (int c = 0; c < CPK; c++) {
        const int o = c * HW;
        float2 a  = *reinterpret_cast<const float2*>(px + o + q0); // x00_0, x00_1(=x10_0)
        float  e0 = px[o + q2];                                    // x10_1
        float2 cc = *reinterpret_cast<const float2*>(px + o + s0); // x01_0, x01_1(=x11_0)
        float  e1 = px[o + s2];                                    // x11_1

        float4 top, bot;
        top.x = a.x;
        top.y = fmaf(c0a.x, a.x, c0a.y * a.y);
        top.z = a.y;
        top.w = fmaf(c1a.x, a.y, c1a.y * e0);
        bot.x = fmaf(c0a.z, a.x, c0a.w * cc.x);
        bot.y = fmaf(c0b.x, a.x, fmaf(c0b.y, a.y, fmaf(c0b.z, cc.x, c0b.w * cc.y)));
        bot.z = fmaf(c1a.z, a.y, c1a.w * cc.y);
        bot.w = fmaf(c1b.x, a.y, fmaf(c1b.y, e0, fmaf(c1b.z, cc.y, c1b.w * e1)));

        const int oo = c * HoWo;
        __stcs(reinterpret_cast<float4*>(po + oo + r0), top);
        __stcs(reinterpret_cast<float4*>(po + oo + r1), bot);
    }
}

extern "C" void kernel_launch(void* const* d_in, const int* in_sizes, int n_in,
                              void* d_out, int out_size) {
    const float* x = (const float*)d_in[0];
    float* out = (float*)d_out;
    (void)in_sizes; (void)n_in; (void)out_size;

    gramcoeff_kernel<<<dim3(H, B), dim3(64, 8)>>>(x);
    upsample_kernel<<<dim3(H / 2, B, ZK), dim3(64, 2)>>>(x, out);
}

// round 9
// speedup vs baseline: 1.4927x; 1.1023x over previous
#include <cuda_runtime.h>

// HBilinearUpsample: Poincare-ball geodesic bilinear upsample (c = 1).
// midpoint(x,y) = P*x + Q*y with (P,Q) from Gram scalars only;
// tanh(atanh(z)/2) = z/(1+sqrt(1-z^2)) -> no transcendentals.
//
// SINGLE fused kernel per (b, h) input row pair:
//   Phase 1: accumulate 7 Gram fields x 2 cells/thread over 8-ch groups
//   Phase 2: smem reduce -> per-cell combination coefficients (smem only)
//   Phase 3: re-load rows (L1/L2 hot) and write both output rows for all
//            64 channels with STG.128 streaming stores.
// No global scratch at all.

static constexpr int B  = 8;
static constexpr int C  = 64;
static constexpr int H  = 128;
static constexpr int W  = 128;
static constexpr int HW = H * W;
static constexpr int CHW = C * HW;
static constexpr int Ho = 2 * H;
static constexpr int Wo = 2 * W;
static constexpr int HoWo = Ho * Wo;

#define EPS_F  1e-15f
#define MAXA_F 0.99999f   // 1 - 1e-5

// ---------------------------------------------------------------------------
// midpoint(x,y) = P*x + Q*y given (|x|^2, |y|^2, <x,y>), c = 1.
// Mirrors the reference clip chain.
// ---------------------------------------------------------------------------
__device__ __forceinline__ void mid_coeffs(float x2, float y2, float xy,
                                           float& P, float& Q) {
    float den1 = fmaxf(1.f - 2.f * xy + x2 * y2, EPS_F);
    float inv1 = __fdividef(1.f, den1);
    float A  = -(1.f - 2.f * xy + y2) * inv1;
    float Bc = (1.f - x2) * inv1;
    float w2 = A * A * x2 + 2.f * A * Bc * xy + Bc * Bc * y2;
    float wn = sqrtf(fmaxf(w2, EPS_F));
    float wc = fminf(wn, MAXA_F);
    float tau = __fdividef(wc, wn * (1.f + sqrtf(fmaxf(1.f - wc * wc, 0.f))));
    float Sa = tau * A;
    float Sb = tau * Bc;
    float xs = tau * (A * x2 + Bc * xy);
    float s2 = tau * tau * w2;
    float k = 1.f + 2.f * xs + s2;
    float den2 = fmaxf(1.f + 2.f * xs + x2 * s2, EPS_F);
    float inv2 = __fdividef(1.f, den2);
    P = (k + (1.f - x2) * Sa) * inv2;
    Q = (1.f - x2) * Sb * inv2;
}

// ---------------------------------------------------------------------------
// Fused kernel. Block (64,8) = 512 threads; grid (H, B).
// tx handles 2 cells (w0 = 2*tx), ty = 8-channel group.
// ---------------------------------------------------------------------------
__global__ void __launch_bounds__(512) fused_kernel(const float* __restrict__ x,
                                                    float* __restrict__ out) {
    const int tx = threadIdx.x;          // 0..63
    const int ty = threadIdx.y;          // 0..7
    const int h  = blockIdx.x;
    const int b  = blockIdx.y;
    const int h1 = min(h + 1, H - 1);
    const int w0 = 2 * tx;
    const int w2 = min(w0 + 2, W - 1);

    const float* base0 = x + b * CHW + ty * 8 * HW + h  * W;
    const float* base1 = x + b * CHW + ty * 8 * HW + h1 * W;

    // ---- Phase 1: Gram accumulation (7 fields x 2 cells) ----
    float nA0=0,nA1=0, nB0=0,nB1=0, hA0=0,hA1=0, hB0=0,hB1=0;
    float v0_=0,v1_=0, g0_=0,g1_=0, a0_=0,a1_=0;

#pragma unroll
    for (int c = 0; c < 8; c++) {
        const int o = c * HW;
        float2 u = *reinterpret_cast<const float2*>(base0 + o + w0);
        float2 d = *reinterpret_cast<const float2*>(base1 + o + w0);
        float eu = base0[o + w2];
        float ed = base1[o + w2];

        nA0 = fmaf(u.x, u.x, nA0);  nA1 = fmaf(u.y, u.y, nA1);
        nB0 = fmaf(d.x, d.x, nB0);  nB1 = fmaf(d.y, d.y, nB1);
        hA0 = fmaf(u.x, u.y, hA0);  hA1 = fmaf(u.y, eu, hA1);
        hB0 = fmaf(d.x, d.y, hB0);  hB1 = fmaf(d.y, ed, hB1);
        v0_ = fmaf(u.x, d.x, v0_);  v1_ = fmaf(u.y, d.y, v1_);
        g0_ = fmaf(u.x, d.y, g0_);  g1_ = fmaf(u.y, ed, g1_);
        a0_ = fmaf(u.y, d.x, a0_);  a1_ = fmaf(eu, d.y, a1_);
    }

    __shared__ float red[8][64][14];
    __shared__ float fin[7][W];
    __shared__ float4 sca[W];   // Pa,Qa,Pv,Qv per cell
    __shared__ float4 scb[W];   // C00,C10,C01,C11 per cell

    float* r = red[ty][tx];
    r[0]=nA0;  r[1]=nA1;
    r[2]=nB0;  r[3]=nB1;
    r[4]=hA0;  r[5]=hA1;
    r[6]=hB0;  r[7]=hB1;
    r[8]=v0_;  r[9]=v1_;
    r[10]=g0_; r[11]=g1_;
    r[12]=a0_; r[13]=a1_;
    __syncthreads();

    // ---- Phase 2a: reduce over the 8 channel groups ----
    const int tid = ty * 64 + tx;
#pragma unroll
    for (int k = tid; k < 7 * W; k += 512) {
        const int f = k >> 7;          // field 0..6
        const int w = k & 127;         // cell column
        const int fj = f * 2 + (w & 1);
        const int xw = w >> 1;
        float s = ((red[0][xw][fj] + red[1][xw][fj]) + (red[2][xw][fj] + red[3][xw][fj]))
                + ((red[4][xw][fj] + red[5][xw][fj]) + (red[6][xw][fj] + red[7][xw][fj]));
        fin[f][w] = s;
    }
    __syncthreads();

    // ---- Phase 2b: per-cell coefficients (128 threads) ----
    if (tid < W) {
        const int w  = tid;
        const int w1 = min(w + 1, W - 1);

        const float n00 = fin[0][w], n10 = fin[0][w1];
        const float n01 = fin[1][w], n11 = fin[1][w1];
        const float dhT = fin[2][w], dhB = fin[3][w];
        const float dvL = fin[4][w], dvR = fin[4][w1];
        const float dgd = fin[5][w], dad = fin[6][w];

        float Pa, Qa, Pv, Qv, Pb, Qb, Pc, Qc;
        mid_coeffs(n00, n10, dhT, Pa, Qa);   // a = mid(x00, x10)
        mid_coeffs(n00, n01, dvL, Pv, Qv);   // mid_v
        mid_coeffs(n01, n11, dhB, Pb, Qb);   // b = mid(x01, x11)

        float a2 = Pa * Pa * n00 + 2.f * Pa * Qa * dhT + Qa * Qa * n10;
        float b2 = Pb * Pb * n01 + 2.f * Pb * Qb * dhB + Qb * Qb * n11;
        float ab = Pa * Pb * dvL + Pa * Qb * dgd + Qa * Pb * dad + Qa * Qb * dvR;
        mid_coeffs(a2, b2, ab, Pc, Qc);      // center = mid(a, b)

        sca[w] = make_float4(Pa, Qa, Pv, Qv);
        scb[w] = make_float4(Pc * Pa, Pc * Qa, Qc * Pb, Qc * Qb);
    }
    __syncthreads();

    // ---- Phase 3: write both output rows for this block's 8 channels ----
    const float4 c0a = sca[w0],     c0b = scb[w0];
    const float4 c1a = sca[w0 + 1], c1b = scb[w0 + 1];

    float* po = out + (size_t)b * C * HoWo + (size_t)ty * 8 * HoWo
                    + (2 * h) * Wo + 4 * tx;

#pragma unroll
    for (int c = 0; c < 8; c++) {
        const int o = c * HW;
        float2 u = *reinterpret_cast<const float2*>(base0 + o + w0);
        float2 d = *reinterpret_cast<const float2*>(base1 + o + w0);
        float eu = base0[o + w2];
        float ed = base1[o + w2];

        float4 top, bot;
        top.x = u.x;
        top.y = fmaf(c0a.x, u.x, c0a.y * u.y);
        top.z = u.y;
        top.w = fmaf(c1a.x, u.y, c1a.y * eu);
        bot.x = fmaf(c0a.z, u.x, c0a.w * d.x);
        bot.y = fmaf(c0b.x, u.x, fmaf(c0b.y, u.y, fmaf(c0b.z, d.x, c0b.w * d.y)));
        bot.z = fmaf(c1a.z, u.y, c1a.w * d.y);
        bot.w = fmaf(c1b.x, u.y, fmaf(c1b.y, eu, fmaf(c1b.z, d.y, c1b.w * ed)));

        float* pc = po + c * HoWo;
        __stcs(reinterpret_cast<float4*>(pc), top);
        __stcs(reinterpret_cast<float4*>(pc + Wo), bot);
    }
}

extern "C" void kernel_launch(void* const* d_in, const int* in_sizes, int n_in,
                              void* d_out, int out_size) {
    const float* x = (const float*)d_in[0];
    float* out = (float*)d_out;
    (void)in_sizes; (void)n_in; (void)out_size;

    fused_kernel<<<dim3(H, B), dim3(64, 8)>>>(x, out);
}

// round 10
// speedup vs baseline: 1.5000x; 1.0049x over previous
#include <cuda_runtime.h>

// HBilinearUpsample: Poincare-ball geodesic bilinear upsample (c = 1).
// midpoint(x,y) = P*x + Q*y with (P,Q) from Gram scalars only;
// tanh(atanh(z)/2) = z/(1+sqrt(1-z^2)) -> no transcendentals.
//
// SINGLE fused kernel, 1 cell/thread (low register pressure):
//   Phase 1: accumulate 7 Gram fields over 16-channel groups (4 groups)
//   Phase 2: smem reduce -> per-cell combination coefficients (smem only)
//   Phase 3: re-load rows (L1 hot) and write both output rows, all 64 ch.
// No global scratch.

static constexpr int B  = 8;
static constexpr int C  = 64;
static constexpr int H  = 128;
static constexpr int W  = 128;
static constexpr int HW = H * W;
static constexpr int CHW = C * HW;
static constexpr int Ho = 2 * H;
static constexpr int Wo = 2 * W;
static constexpr int HoWo = Ho * Wo;

#define EPS_F  1e-15f
#define MAXA_F 0.99999f   // 1 - 1e-5

// ---------------------------------------------------------------------------
// midpoint(x,y) = P*x + Q*y given (|x|^2, |y|^2, <x,y>), c = 1.
// Mirrors the reference clip chain.
// ---------------------------------------------------------------------------
__device__ __forceinline__ void mid_coeffs(float x2, float y2, float xy,
                                           float& P, float& Q) {
    float den1 = fmaxf(1.f - 2.f * xy + x2 * y2, EPS_F);
    float inv1 = __fdividef(1.f, den1);
    float A  = -(1.f - 2.f * xy + y2) * inv1;
    float Bc = (1.f - x2) * inv1;
    float w2 = A * A * x2 + 2.f * A * Bc * xy + Bc * Bc * y2;
    float wn = sqrtf(fmaxf(w2, EPS_F));
    float wc = fminf(wn, MAXA_F);
    float tau = __fdividef(wc, wn * (1.f + sqrtf(fmaxf(1.f - wc * wc, 0.f))));
    float Sa = tau * A;
    float Sb = tau * Bc;
    float xs = tau * (A * x2 + Bc * xy);
    float s2 = tau * tau * w2;
    float k = 1.f + 2.f * xs + s2;
    float den2 = fmaxf(1.f + 2.f * xs + x2 * s2, EPS_F);
    float inv2 = __fdividef(1.f, den2);
    P = (k + (1.f - x2) * Sa) * inv2;
    Q = (1.f - x2) * Sb * inv2;
}

// ---------------------------------------------------------------------------
// Fused kernel. Block (128,4) = 512 threads; grid (H, B).
// tx = cell w, ty = 16-channel group.
// ---------------------------------------------------------------------------
__global__ void __launch_bounds__(512, 3) fused_kernel(const float* __restrict__ x,
                                                       float* __restrict__ out) {
    const int w  = threadIdx.x;          // 0..127
    const int ty = threadIdx.y;          // 0..3
    const int h  = blockIdx.x;
    const int b  = blockIdx.y;
    const int h1 = min(h + 1, H - 1);
    const int w1 = min(w + 1, W - 1);

    const float* base0 = x + b * CHW + ty * 16 * HW + h  * W;
    const float* base1 = x + b * CHW + ty * 16 * HW + h1 * W;

    // ---- Phase 1: Gram accumulation (7 fields, 1 cell) ----
    float nA=0, nB=0, hA=0, hB=0, vv=0, gg=0, aa=0;

#pragma unroll 4
    for (int c = 0; c < 16; c++) {
        const int o = c * HW;
        float u  = base0[o + w];
        float d  = base1[o + w];
        float eu = base0[o + w1];
        float ed = base1[o + w1];

        nA = fmaf(u,  u,  nA);
        nB = fmaf(d,  d,  nB);
        hA = fmaf(u,  eu, hA);
        hB = fmaf(d,  ed, hB);
        vv = fmaf(u,  d,  vv);
        gg = fmaf(u,  ed, gg);
        aa = fmaf(eu, d,  aa);
    }

    __shared__ float red[4][7][128];
    __shared__ float fin[7][W];
    __shared__ float4 sca[W];   // Pa,Qa,Pv,Qv per cell
    __shared__ float4 scb[W];   // C00,C10,C01,C11 per cell

    red[ty][0][w] = nA;
    red[ty][1][w] = nB;
    red[ty][2][w] = hA;
    red[ty][3][w] = hB;
    red[ty][4][w] = vv;
    red[ty][5][w] = gg;
    red[ty][6][w] = aa;
    __syncthreads();

    // ---- Phase 2a: reduce over the 4 channel groups ----
    const int tid = ty * 128 + w;
#pragma unroll
    for (int k = tid; k < 7 * W; k += 512) {
        const int f = k >> 7;          // field 0..6
        const int wc = k & 127;        // cell column
        fin[f][wc] = (red[0][f][wc] + red[1][f][wc]) + (red[2][f][wc] + red[3][f][wc]);
    }
    __syncthreads();

    // ---- Phase 2b: per-cell coefficients (128 threads) ----
    if (tid < W) {
        const int ww  = tid;
        const int ww1 = min(ww + 1, W - 1);

        const float n00 = fin[0][ww], n10 = fin[0][ww1];
        const float n01 = fin[1][ww], n11 = fin[1][ww1];
        const float dhT = fin[2][ww], dhB = fin[3][ww];
        const float dvL = fin[4][ww], dvR = fin[4][ww1];
        const float dgd = fin[5][ww], dad = fin[6][ww];

        float Pa, Qa, Pv, Qv, Pb, Qb, Pc, Qc;
        mid_coeffs(n00, n10, dhT, Pa, Qa);   // a = mid(x00, x10)
        mid_coeffs(n00, n01, dvL, Pv, Qv);   // mid_v
        mid_coeffs(n01, n11, dhB, Pb, Qb);   // b = mid(x01, x11)

        float a2 = Pa * Pa * n00 + 2.f * Pa * Qa * dhT + Qa * Qa * n10;
        float b2 = Pb * Pb * n01 + 2.f * Pb * Qb * dhB + Qb * Qb * n11;
        float ab = Pa * Pb * dvL + Pa * Qb * dgd + Qa * Pb * dad + Qa * Qb * dvR;
        mid_coeffs(a2, b2, ab, Pc, Qc);      // center = mid(a, b)

        sca[ww] = make_float4(Pa, Qa, Pv, Qv);
        scb[ww] = make_float4(Pc * Pa, Pc * Qa, Qc * Pb, Qc * Qb);
    }
    __syncthreads();

    // ---- Phase 3: write both output rows for this group's 16 channels ----
    const float4 ka = sca[w];
    const float4 kb = scb[w];

    float* po = out + (size_t)b * C * HoWo + (size_t)ty * 16 * HoWo
                    + (2 * h) * Wo + 2 * w;

#pragma unroll 4
    for (int c = 0; c < 16; c++) {
        const int o = c * HW;
        float u  = base0[o + w];
        float d  = base1[o + w];
        float eu = base0[o + w1];
        float ed = base1[o + w1];

        float2 top, bot;
        top.x = u;
        top.y = fmaf(ka.x, u, ka.y * eu);
        bot.x = fmaf(ka.z, u, ka.w * d);
        bot.y = fmaf(kb.x, u, fmaf(kb.y, eu, fmaf(kb.z, d, kb.w * ed)));

        float* pc = po + c * HoWo;
        __stcs(reinterpret_cast<float2*>(pc), top);
        __stcs(reinterpret_cast<float2*>(pc + Wo), bot);
    }
}

extern "C" void kernel_launch(void* const* d_in, const int* in_sizes, int n_in,
                              void* d_out, int out_size) {
    const float* x = (const float*)d_in[0];
    float* out = (float*)d_out;
    (void)in_sizes; (void)n_in; (void)out_size;

    fused_kernel<<<dim3(H, B), dim3(128, 4)>>>(x, out);
}

// round 11
// speedup vs baseline: 1.5922x; 1.0615x over previous
#include <cuda_runtime.h>

// HBilinearUpsample: Poincare-ball geodesic bilinear upsample (c = 1).
// midpoint(x,y) = P*x + Q*y with (P,Q) from Gram scalars only;
// tanh(atanh(z)/2) = z/(1+sqrt(1-z^2)) -> no transcendentals.
//
// Fused single kernel, smem-staged:
//   Phase 0: stage rows h, h+1 (all 64 ch) into smem via coalesced LDG.128
//   Phase 1: 4 warps accumulate the 7 Gram fields from smem (LDS)
//   Phase 2: 128 threads compute per-cell combination coefficients (smem)
//   Phase 3: all 16 warps emit both output rows with STG.128 streaming
// No global scratch; LSU instruction count minimized (LDG.128 + STG.128).

static constexpr int B  = 8;
static constexpr int C  = 64;
static constexpr int H  = 128;
static constexpr int W  = 128;
static constexpr int HW = H * W;
static constexpr int CHW = C * HW;
static constexpr int Ho = 2 * H;
static constexpr int Wo = 2 * W;
static constexpr int HoWo = Ho * Wo;

static constexpr int SMEM_TILE_BYTES = 2 * C * W * 4;   // 65536

#define EPS_F  1e-15f
#define MAXA_F 0.99999f   // 1 - 1e-5

// ---------------------------------------------------------------------------
// midpoint(x,y) = P*x + Q*y given (|x|^2, |y|^2, <x,y>), c = 1.
// Mirrors the reference clip chain.
// ---------------------------------------------------------------------------
__device__ __forceinline__ void mid_coeffs(float x2, float y2, float xy,
                                           float& P, float& Q) {
    float den1 = fmaxf(1.f - 2.f * xy + x2 * y2, EPS_F);
    float inv1 = __fdividef(1.f, den1);
    float A  = -(1.f - 2.f * xy + y2) * inv1;
    float Bc = (1.f - x2) * inv1;
    float w2 = A * A * x2 + 2.f * A * Bc * xy + Bc * Bc * y2;
    float wn = sqrtf(fmaxf(w2, EPS_F));
    float wc = fminf(wn, MAXA_F);
    float tau = __fdividef(wc, wn * (1.f + sqrtf(fmaxf(1.f - wc * wc, 0.f))));
    float Sa = tau * A;
    float Sb = tau * Bc;
    float xs = tau * (A * x2 + Bc * xy);
    float s2 = tau * tau * w2;
    float k = 1.f + 2.f * xs + s2;
    float den2 = fmaxf(1.f + 2.f * xs + x2 * s2, EPS_F);
    float inv2 = __fdividef(1.f, den2);
    P = (k + (1.f - x2) * Sa) * inv2;
    Q = (1.f - x2) * Sb * inv2;
}

// ---------------------------------------------------------------------------
// Fused kernel. 512 threads; grid (H, B).
// smem tile layout: s[(r*64 + c)*128 + w], r in {0,1} = rows {h, h1}.
// ---------------------------------------------------------------------------
__global__ void __launch_bounds__(512) fused_kernel(const float* __restrict__ x,
                                                    float* __restrict__ out) {
    extern __shared__ float s[];
    __shared__ float  fin[7][W];
    __shared__ float4 sca[W];   // Pa,Qa,Pv,Qv per cell
    __shared__ float4 scb[W];   // C00,C10,C01,C11 per cell

    const int tid = threadIdx.x;
    const int h   = blockIdx.x;
    const int b   = blockIdx.y;
    const int h1  = min(h + 1, H - 1);

    // ---- Phase 0: stage both rows, all channels (coalesced LDG.128) ----
    const float* xb = x + b * CHW;
    {
        const int row_off[2] = { h * W, h1 * W };
#pragma unroll
        for (int k = 0; k < 8; k++) {
            const int i  = tid + k * 512;     // float4 index 0..4095
            const int j  = (i & 31) * 4;      // float offset within row
            const int rc = i >> 5;            // row-channel 0..127
            const int c  = rc & 63;
            const int r  = rc >> 6;
            float4 v = *reinterpret_cast<const float4*>(xb + c * HW + row_off[r] + j);
            *reinterpret_cast<float4*>(&s[rc * W + j]) = v;
        }
    }
    __syncthreads();

    // ---- Phase 1: Gram accumulation from smem (warps 0-3 only) ----
    if (tid < W) {
        const int w  = tid;
        const int w1 = min(w + 1, W - 1);
        float nA=0, nB=0, hA=0, hB=0, vv=0, gg=0, aa=0;
#pragma unroll 4
        for (int c = 0; c < C; c++) {
            float u  = s[c * W + w];
            float eu = s[c * W + w1];
            float d  = s[(C + c) * W + w];
            float ed = s[(C + c) * W + w1];
            nA = fmaf(u,  u,  nA);
            nB = fmaf(d,  d,  nB);
            hA = fmaf(u,  eu, hA);
            hB = fmaf(d,  ed, hB);
            vv = fmaf(u,  d,  vv);
            gg = fmaf(u,  ed, gg);
            aa = fmaf(eu, d,  aa);
        }
        fin[0][w] = nA;
        fin[1][w] = nB;
        fin[2][w] = hA;
        fin[3][w] = hB;
        fin[4][w] = vv;
        fin[5][w] = gg;
        fin[6][w] = aa;
    }
    __syncthreads();

    // ---- Phase 2: per-cell coefficients (warps 0-3) ----
    if (tid < W) {
        const int w  = tid;
        const int w1 = min(w + 1, W - 1);

        const float n00 = fin[0][w], n10 = fin[0][w1];
        const float n01 = fin[1][w], n11 = fin[1][w1];
        const float dhT = fin[2][w], dhB = fin[3][w];
        const float dvL = fin[4][w], dvR = fin[4][w1];
        const float dgd = fin[5][w], dad = fin[6][w];

        float Pa, Qa, Pv, Qv, Pb, Qb, Pc, Qc;
        mid_coeffs(n00, n10, dhT, Pa, Qa);   // a = mid(x00, x10)
        mid_coeffs(n00, n01, dvL, Pv, Qv);   // mid_v
        mid_coeffs(n01, n11, dhB, Pb, Qb);   // b = mid(x01, x11)

        float a2 = Pa * Pa * n00 + 2.f * Pa * Qa * dhT + Qa * Qa * n10;
        float b2 = Pb * Pb * n01 + 2.f * Pb * Qb * dhB + Qb * Qb * n11;
        float ab = Pa * Pb * dvL + Pa * Qb * dgd + Qa * Pb * dad + Qa * Qb * dvR;
        mid_coeffs(a2, b2, ab, Pc, Qc);      // center = mid(a, b)

        sca[w] = make_float4(Pa, Qa, Pv, Qv);
        scb[w] = make_float4(Pc * Pa, Pc * Qa, Qc * Pb, Qc * Qb);
    }
    __syncthreads();

    // ---- Phase 3: write both output rows (all 16 warps, STG.128) ----
    const int lw = tid & 63;      // 2-cell column group: w0 = 2*lw
    const int cg = tid >> 6;      // channel group 0..7 (8 channels each)
    const int w0 = 2 * lw;
    const int w2 = min(w0 + 2, W - 1);

    const float4 k0a = sca[w0],     k0b = scb[w0];
    const float4 k1a = sca[w0 + 1], k1b = scb[w0 + 1];

    float* po = out + (size_t)b * C * HoWo + (size_t)cg * 8 * HoWo
                    + (2 * h) * Wo + 4 * lw;

#pragma unroll 2
    for (int i = 0; i < 8; i++) {
        const int c = cg * 8 + i;
        float2 u = *reinterpret_cast<const float2*>(&s[c * W + w0]);
        float eu = s[c * W + w2];
        float2 d = *reinterpret_cast<const float2*>(&s[(C + c) * W + w0]);
        float ed = s[(C + c) * W + w2];

        float4 top, bot;
        top.x = u.x;
        top.y = fmaf(k0a.x, u.x, k0a.y * u.y);
        top.z = u.y;
        top.w = fmaf(k1a.x, u.y, k1a.y * eu);
        bot.x = fmaf(k0a.z, u.x, k0a.w * d.x);
        bot.y = fmaf(k0b.x, u.x, fmaf(k0b.y, u.y, fmaf(k0b.z, d.x, k0b.w * d.y)));
        bot.z = fmaf(k1a.z, u.y, k1a.w * d.y);
        bot.w = fmaf(k1b.x, u.y, fmaf(k1b.y, eu, fmaf(k1b.z, d.y, k1b.w * ed)));

        float* pc = po + (size_t)i * HoWo;
        __stcs(reinterpret_cast<float4*>(pc), top);
        __stcs(reinterpret_cast<float4*>(pc + Wo), bot);
    }
}

extern "C" void kernel_launch(void* const* d_in, const int* in_sizes, int n_in,
                              void* d_out, int out_size) {
    const float* x = (const float*)d_in[0];
    float* out = (float*)d_out;
    (void)in_sizes; (void)n_in; (void)out_size;

    cudaFuncSetAttribute(fused_kernel,
                         cudaFuncAttributeMaxDynamicSharedMemorySize,
                         SMEM_TILE_BYTES);
    fused_kernel<<<dim3(H, B), 512, SMEM_TILE_BYTES>>>(x, out);
}

// round 12
// speedup vs baseline: 1.6673x; 1.0471x over previous
#include <cuda_runtime.h>

// HBilinearUpsample: Poincare-ball geodesic bilinear upsample (c = 1).
// midpoint(x,y) = P*x + Q*y with (P,Q) from Gram scalars only;
// tanh(atanh(z)/2) = z/(1+sqrt(1-z^2)) -> no transcendentals.
//
// Fused single kernel, smem-staged:
//   Phase 0: stage rows h, h+1 (all 64 ch) into smem via coalesced LDG.128
//   Phase 1: ALL 16 warps accumulate Gram fields, partitioned BY FIELD
//            (no reduction array, no extra smem, 4x parallel vs R11)
//   Phase 2: 128 threads compute per-cell combination coefficients
//   Phase 3: all 16 warps emit both output rows with STG.128 streaming

static constexpr int B  = 8;
static constexpr int C  = 64;
static constexpr int H  = 128;
static constexpr int W  = 128;
static constexpr int HW = H * W;
static constexpr int CHW = C * HW;
static constexpr int Ho = 2 * H;
static constexpr int Wo = 2 * W;
static constexpr int HoWo = Ho * Wo;

static constexpr int SMEM_TILE_BYTES = 2 * C * W * 4;   // 65536

#define EPS_F  1e-15f
#define MAXA_F 0.99999f   // 1 - 1e-5

// ---------------------------------------------------------------------------
// midpoint(x,y) = P*x + Q*y given (|x|^2, |y|^2, <x,y>), c = 1.
// Mirrors the reference clip chain.
// ---------------------------------------------------------------------------
__device__ __forceinline__ void mid_coeffs(float x2, float y2, float xy,
                                           float& P, float& Q) {
    float den1 = fmaxf(1.f - 2.f * xy + x2 * y2, EPS_F);
    float inv1 = __fdividef(1.f, den1);
    float A  = -(1.f - 2.f * xy + y2) * inv1;
    float Bc = (1.f - x2) * inv1;
    float w2 = A * A * x2 + 2.f * A * Bc * xy + Bc * Bc * y2;
    float wn = sqrtf(fmaxf(w2, EPS_F));
    float wc = fminf(wn, MAXA_F);
    float tau = __fdividef(wc, wn * (1.f + sqrtf(fmaxf(1.f - wc * wc, 0.f))));
    float Sa = tau * A;
    float Sb = tau * Bc;
    float xs = tau * (A * x2 + Bc * xy);
    float s2 = tau * tau * w2;
    float k = 1.f + 2.f * xs + s2;
    float den2 = fmaxf(1.f + 2.f * xs + x2 * s2, EPS_F);
    float inv2 = __fdividef(1.f, den2);
    P = (k + (1.f - x2) * Sa) * inv2;
    Q = (1.f - x2) * Sb * inv2;
}

// ---------------------------------------------------------------------------
// Fused kernel. 512 threads; grid (H, B).
// smem tile layout: s[(r*64 + c)*128 + w], r in {0,1} = rows {h, h1}.
// ---------------------------------------------------------------------------
__global__ void __launch_bounds__(512) fused_kernel(const float* __restrict__ x,
                                                    float* __restrict__ out) {
    extern __shared__ float s[];
    __shared__ float  fin[7][W];
    __shared__ float4 sca[W];   // Pa,Qa,Pv,Qv per cell
    __shared__ float4 scb[W];   // C00,C10,C01,C11 per cell

    const int tid = threadIdx.x;
    const int h   = blockIdx.x;
    const int b   = blockIdx.y;
    const int h1  = min(h + 1, H - 1);

    // ---- Phase 0: stage both rows, all channels (coalesced LDG.128) ----
    const float* xb = x + b * CHW;
    {
        const int row_off[2] = { h * W, h1 * W };
#pragma unroll
        for (int k = 0; k < 8; k++) {
            const int i  = tid + k * 512;     // float4 index 0..4095
            const int j  = (i & 31) * 4;      // float offset within row
            const int rc = i >> 5;            // row-channel 0..127
            const int c  = rc & 63;
            const int r  = rc >> 6;
            float4 v = *reinterpret_cast<const float4*>(xb + c * HW + row_off[r] + j);
            *reinterpret_cast<float4*>(&s[rc * W + j]) = v;
        }
    }
    __syncthreads();

    // ---- Phase 1: Gram accumulation, field-partitioned across 4 groups ----
    {
        const int w  = tid & 127;
        const int tg = tid >> 7;             // 0..3
        const int w1 = min(w + 1, W - 1);

        if (tg == 0) {                        // needs u, eu
            float nA = 0.f, hA = 0.f;
#pragma unroll 8
            for (int c = 0; c < C; c++) {
                float u  = s[c * W + w];
                float eu = s[c * W + w1];
                nA = fmaf(u, u,  nA);
                hA = fmaf(u, eu, hA);
            }
            fin[0][w] = nA;
            fin[2][w] = hA;
        } else if (tg == 1) {                 // needs d, ed
            float nB = 0.f, hB = 0.f;
#pragma unroll 8
            for (int c = 0; c < C; c++) {
                float d  = s[(C + c) * W + w];
                float ed = s[(C + c) * W + w1];
                nB = fmaf(d, d,  nB);
                hB = fmaf(d, ed, hB);
            }
            fin[1][w] = nB;
            fin[3][w] = hB;
        } else if (tg == 2) {                 // needs u, d, ed
            float vv = 0.f, gg = 0.f;
#pragma unroll 8
            for (int c = 0; c < C; c++) {
                float u  = s[c * W + w];
                float d  = s[(C + c) * W + w];
                float ed = s[(C + c) * W + w1];
                vv = fmaf(u, d,  vv);
                gg = fmaf(u, ed, gg);
            }
            fin[4][w] = vv;
            fin[5][w] = gg;
        } else {                              // needs eu, d
            float aa = 0.f;
#pragma unroll 8
            for (int c = 0; c < C; c++) {
                float eu = s[c * W + w1];
                float d  = s[(C + c) * W + w];
                aa = fmaf(eu, d, aa);
            }
            fin[6][w] = aa;
        }
    }
    __syncthreads();

    // ---- Phase 2: per-cell coefficients (warps 0-3) ----
    if (tid < W) {
        const int w  = tid;
        const int w1 = min(w + 1, W - 1);

        const float n00 = fin[0][w], n10 = fin[0][w1];
        const float n01 = fin[1][w], n11 = fin[1][w1];
        const float dhT = fin[2][w], dhB = fin[3][w];
        const float dvL = fin[4][w], dvR = fin[4][w1];
        const float dgd = fin[5][w], dad = fin[6][w];

        float Pa, Qa, Pv, Qv, Pb, Qb, Pc, Qc;
        mid_coeffs(n00, n10, dhT, Pa, Qa);   // a = mid(x00, x10)
        mid_coeffs(n00, n01, dvL, Pv, Qv);   // mid_v
        mid_coeffs(n01, n11, dhB, Pb, Qb);   // b = mid(x01, x11)

        float a2 = Pa * Pa * n00 + 2.f * Pa * Qa * dhT + Qa * Qa * n10;
        float b2 = Pb * Pb * n01 + 2.f * Pb * Qb * dhB + Qb * Qb * n11;
        float ab = Pa * Pb * dvL + Pa * Qb * dgd + Qa * Pb * dad + Qa * Qb * dvR;
        mid_coeffs(a2, b2, ab, Pc, Qc);      // center = mid(a, b)

        sca[w] = make_float4(Pa, Qa, Pv, Qv);
        scb[w] = make_float4(Pc * Pa, Pc * Qa, Qc * Pb, Qc * Qb);
    }
    __syncthreads();

    // ---- Phase 3: write both output rows (all 16 warps, STG.128) ----
    const int lw = tid & 63;      // 2-cell column group: w0 = 2*lw
    const int cg = tid >> 6;      // channel group 0..7 (8 channels each)
    const int w0 = 2 * lw;
    const int w2 = min(w0 + 2, W - 1);

    const float4 k0a = sca[w0],     k0b = scb[w0];
    const float4 k1a = sca[w0 + 1], k1b = scb[w0 + 1];

    float* po = out + (size_t)b * C * HoWo + (size_t)cg * 8 * HoWo
                    + (2 * h) * Wo + 4 * lw;

#pragma unroll 2
    for (int i = 0; i < 8; i++) {
        const int c = cg * 8 + i;
        float2 u = *reinterpret_cast<const float2*>(&s[c * W + w0]);
        float eu = s[c * W + w2];
        float2 d = *reinterpret_cast<const float2*>(&s[(C + c) * W + w0]);
        float ed = s[(C + c) * W + w2];

        float4 top, bot;
        top.x = u.x;
        top.y = fmaf(k0a.x, u.x, k0a.y * u.y);
        top.z = u.y;
        top.w = fmaf(k1a.x, u.y, k1a.y * eu);
        bot.x = fmaf(k0a.z, u.x, k0a.w * d.x);
        bot.y = fmaf(k0b.x, u.x, fmaf(k0b.y, u.y, fmaf(k0b.z, d.x, k0b.w * d.y)));
        bot.z = fmaf(k1a.z, u.y, k1a.w * d.y);
        bot.w = fmaf(k1b.x, u.y, fmaf(k1b.y, eu, fmaf(k1b.z, d.y, k1b.w * ed)));

        float* pc = po + (size_t)i * HoWo;
        __stcs(reinterpret_cast<float4*>(pc), top);
        __stcs(reinterpret_cast<float4*>(pc + Wo), bot);
    }
}

extern "C" void kernel_launch(void* const* d_in, const int* in_sizes, int n_in,
                              void* d_out, int out_size) {
    const float* x = (const float*)d_in[0];
    float* out = (float*)d_out;
    (void)in_sizes; (void)n_in; (void)out_size;

    cudaFuncSetAttribute(fused_kernel,
                         cudaFuncAttributeMaxDynamicSharedMemorySize,
                         SMEM_TILE_BYTES);
    fused_kernel<<<dim3(H, B), 512, SMEM_TILE_BYTES>>>(x, out);
}

// round 13
// speedup vs baseline: 1.7683x; 1.0606x over previous
#include <cuda_runtime.h>

// HBilinearUpsample: Poincare-ball geodesic bilinear upsample (c = 1).
// midpoint(x,y) = P*x + Q*y with (P,Q) from Gram scalars only;
// tanh(atanh(z)/2) = z/(1+sqrt(1-z^2)) -> no transcendentals.
//
// Fused single kernel, smem-staged with 16-float XOR swizzle:
//   Phase 0: stage rows h, h+1 (all 64 ch) into smem via coalesced LDG.128
//   Phase 1: all 16 warps: each lane owns one cell x 16 channels, computes
//            ALL 7 Gram fields, then shfl_xor-reduces over 4 channel groups
//   Phase 2: 3 independent midpoints on 384 threads, then center on 128
//   Phase 3: all 16 warps emit both output rows with STG.128 streaming

static constexpr int B  = 8;
static constexpr int C  = 64;
static constexpr int H  = 128;
static constexpr int W  = 128;
static constexpr int HW = H * W;
static constexpr int CHW = C * HW;
static constexpr int Ho = 2 * H;
static constexpr int Wo = 2 * W;
static constexpr int HoWo = Ho * Wo;

static constexpr int SMEM_TILE_BYTES = 2 * C * W * 4;   // 65536

#define EPS_F  1e-15f
#define MAXA_F 0.99999f   // 1 - 1e-5

// ---------------------------------------------------------------------------
// midpoint(x,y) = P*x + Q*y given (|x|^2, |y|^2, <x,y>), c = 1.
// Mirrors the reference clip chain.
// ---------------------------------------------------------------------------
__device__ __forceinline__ void mid_coeffs(float x2, float y2, float xy,
                                           float& P, float& Q) {
    float den1 = fmaxf(1.f - 2.f * xy + x2 * y2, EPS_F);
    float inv1 = __fdividef(1.f, den1);
    float A  = -(1.f - 2.f * xy + y2) * inv1;
    float Bc = (1.f - x2) * inv1;
    float w2 = A * A * x2 + 2.f * A * Bc * xy + Bc * Bc * y2;
    float wn = sqrtf(fmaxf(w2, EPS_F));
    float wc = fminf(wn, MAXA_F);
    float tau = __fdividef(wc, wn * (1.f + sqrtf(fmaxf(1.f - wc * wc, 0.f))));
    float Sa = tau * A;
    float Sb = tau * Bc;
    float xs = tau * (A * x2 + Bc * xy);
    float s2 = tau * tau * w2;
    float k = 1.f + 2.f * xs + s2;
    float den2 = fmaxf(1.f + 2.f * xs + x2 * s2, EPS_F);
    float inv2 = __fdividef(1.f, den2);
    P = (k + (1.f - x2) * Sa) * inv2;
    Q = (1.f - x2) * Sb * inv2;
}

// ---------------------------------------------------------------------------
// Fused kernel. 512 threads; grid (H, B).
// smem tile: s[rc*128 + (w ^ 8*(c&3))], rc = r*64+c, r in {0,1} rows {h,h1}.
// The XOR swizzle makes phase-1's 4-channel-group column reads conflict-free
// while keeping float4/float2 accesses aligned (XOR operand multiple of 8).
// ---------------------------------------------------------------------------
__global__ void __launch_bounds__(512) fused_kernel(const float* __restrict__ x,
                                                    float* __restrict__ out) {
    extern __shared__ float s[];
    __shared__ float  fin[7][W];
    __shared__ __align__(16) float2 sca2[W][2];  // [w][0]=(Pa,Qa) [w][1]=(Pv,Qv)
    __shared__ float4 scb[W];                    // C00,C10,C01,C11
    __shared__ float2 spqb[W];                   // (Pb,Qb) handoff

    const int tid = threadIdx.x;
    const int h   = blockIdx.x;
    const int b   = blockIdx.y;
    const int h1  = min(h + 1, H - 1);

    // ---- Phase 0: stage both rows, all channels (coalesced LDG.128) ----
    const float* xb = x + b * CHW;
    {
        const int row_off[2] = { h * W, h1 * W };
#pragma unroll
        for (int k = 0; k < 8; k++) {
            const int i  = tid + k * 512;     // float4 index 0..4095
            const int j  = (i & 31) * 4;      // float offset within row
            const int rc = i >> 5;            // row-channel 0..127
            const int c  = rc & 63;
            const int r  = rc >> 6;
            const int m  = (c & 3) * 8;       // swizzle
            float4 v = *reinterpret_cast<const float4*>(xb + c * HW + row_off[r] + j);
            *reinterpret_cast<float4*>(&s[rc * W + (j ^ m)]) = v;
        }
    }
    __syncthreads();

    // ---- Phase 1: all-field Gram, warp-internal channel reduction ----
    {
        const int lane = tid & 31;
        const int wp   = tid >> 5;        // warp 0..15
        const int dw   = lane >> 2;       // cell within warp 0..7
        const int cg   = lane & 3;        // channel group 0..3
        const int w    = wp * 8 + dw;
        const int w1   = min(w + 1, W - 1);
        const int m    = cg * 8;
        const int o_u  = (w  ^ m);
        const int o_e  = (w1 ^ m);

        float nA=0, nB=0, hA=0, hB=0, vv=0, gg=0, aa=0;
#pragma unroll 4
        for (int i = 0; i < 16; i++) {
            const int c = 4 * i + cg;     // c & 3 == cg -> swizzle m matches
            const float* r0 = s + c * W;
            const float* r1 = s + (C + c) * W;
            float u  = r0[o_u];
            float eu = r0[o_e];
            float d  = r1[o_u];
            float ed = r1[o_e];
            nA = fmaf(u,  u,  nA);
            nB = fmaf(d,  d,  nB);
            hA = fmaf(u,  eu, hA);
            hB = fmaf(d,  ed, hB);
            vv = fmaf(u,  d,  vv);
            gg = fmaf(u,  ed, gg);
            aa = fmaf(eu, d,  aa);
        }
        // reduce over the 4 channel groups (lanes differing in bits 0-1)
#define RED4(v) v += __shfl_xor_sync(0xffffffffu, v, 1); \
                v += __shfl_xor_sync(0xffffffffu, v, 2);
        RED4(nA) RED4(nB) RED4(hA) RED4(hB) RED4(vv) RED4(gg) RED4(aa)
#undef RED4
        if (cg == 0) {
            fin[0][w] = nA;
            fin[1][w] = nB;
            fin[2][w] = hA;
            fin[3][w] = hB;
            fin[4][w] = vv;
            fin[5][w] = gg;
            fin[6][w] = aa;
        }
    }
    __syncthreads();

    // ---- Phase 2a: three independent midpoints on 384 threads ----
    {
        const int g = tid >> 7;           // 0..3
        const int w = tid & 127;
        const int w1 = min(w + 1, W - 1);
        if (g == 0) {                     // a = mid(x00, x10)
            float P, Q;
            mid_coeffs(fin[0][w], fin[0][w1], fin[2][w], P, Q);
            sca2[w][0] = make_float2(P, Q);
        } else if (g == 1) {              // mid_v = mid(x00, x01)
            float P, Q;
            mid_coeffs(fin[0][w], fin[1][w], fin[4][w], P, Q);
            sca2[w][1] = make_float2(P, Q);
        } else if (g == 2) {              // b = mid(x01, x11)
            float P, Q;
            mid_coeffs(fin[1][w], fin[1][w1], fin[3][w], P, Q);
            spqb[w] = make_float2(P, Q);
        }
    }
    __syncthreads();

    // ---- Phase 2b: center midpoint + combine (128 threads) ----
    if (tid < W) {
        const int w  = tid;
        const int w1 = min(w + 1, W - 1);

        const float2 pa = sca2[w][0];     // Pa, Qa
        const float2 pb = spqb[w];        // Pb, Qb
        const float n00 = fin[0][w], n10 = fin[0][w1];
        const float n01 = fin[1][w], n11 = fin[1][w1];
        const float dhT = fin[2][w], dhB = fin[3][w];
        const float dvL = fin[4][w], dvR = fin[4][w1];
        const float dgd = fin[5][w], dad = fin[6][w];

        float a2 = pa.x * pa.x * n00 + 2.f * pa.x * pa.y * dhT + pa.y * pa.y * n10;
        float b2 = pb.x * pb.x * n01 + 2.f * pb.x * pb.y * dhB + pb.y * pb.y * n11;
        float ab = pa.x * pb.x * dvL + pa.x * pb.y * dgd
                 + pa.y * pb.x * dad + pa.y * pb.y * dvR;
        float Pc, Qc;
        mid_coeffs(a2, b2, ab, Pc, Qc);   // center = mid(a, b)

        scb[w] = make_float4(Pc * pa.x, Pc * pa.y, Qc * pb.x, Qc * pb.y);
    }
    __syncthreads();

    // ---- Phase 3: write both output rows (all 16 warps, STG.128) ----
    const int lw = tid & 63;      // 2-cell column group: w0 = 2*lw
    const int cg = tid >> 6;      // channel group 0..7 (8 channels each)
    const int w0 = 2 * lw;
    const int w2 = min(w0 + 2, W - 1);

    const float4 k0a = *reinterpret_cast<const float4*>(&sca2[w0][0]);
    const float4 k1a = *reinterpret_cast<const float4*>(&sca2[w0 + 1][0]);
    const float4 k0b = scb[w0];
    const float4 k1b = scb[w0 + 1];

    float* po = out + (size_t)b * C * HoWo + (size_t)cg * 8 * HoWo
                    + (2 * h) * Wo + 4 * lw;

#pragma unroll 2
    for (int i = 0; i < 8; i++) {
        const int c = cg * 8 + i;
        const int m = (c & 3) * 8;
        const float* r0 = s + c * W;
        const float* r1 = s + (C + c) * W;
        float2 u = *reinterpret_cast<const float2*>(&r0[w0 ^ m]);
        float eu = r0[w2 ^ m];
        float2 d = *reinterpret_cast<const float2*>(&r1[w0 ^ m]);
        float ed = r1[w2 ^ m];

        float4 top, bot;
        top.x = u.x;
        top.y = fmaf(k0a.x, u.x, k0a.y * u.y);
        top.z = u.y;
        top.w = fmaf(k1a.x, u.y, k1a.y * eu);
        bot.x = fmaf(k0a.z, u.x, k0a.w * d.x);
        bot.y = fmaf(k0b.x, u.x, fmaf(k0b.y, u.y, fmaf(k0b.z, d.x, k0b.w * d.y)));
        bot.z = fmaf(k1a.z, u.y, k1a.w * d.y);
        bot.w = fmaf(k1b.x, u.y, fmaf(k1b.y, eu, fmaf(k1b.z, d.y, k1b.w * ed)));

        float* pc = po + (size_t)i * HoWo;
        __stcs(reinterpret_cast<float4*>(pc), top);
        __stcs(reinterpret_cast<float4*>(pc + Wo), bot);
    }
}

extern "C" void kernel_launch(void* const* d_in, const int* in_sizes, int n_in,
                              void* d_out, int out_size) {
    const float* x = (const float*)d_in[0];
    float* out = (float*)d_out;
    (void)in_sizes; (void)n_in; (void)out_size;

    cudaFuncSetAttribute(fused_kernel,
                         cudaFuncAttributeMaxDynamicSharedMemorySize,
                         SMEM_TILE_BYTES);
    fused_kernel<<<dim3(H, B), 512, SMEM_TILE_BYTES>>>(x, out);
}